// round 6
// baseline (speedup 1.0000x reference)
#include <cuda_runtime.h>

#define NN      256
#define DD      64
#define NH      4
#define DHD     32
#define NINNER  128
#define NOUT    516   // 384 qkv + 128 gate + 4 bias
#define ATT_SCALE 0.17677669529663687f  // 1/sqrt(32)

// ---------------- scratch (device globals: sanctioned, no runtime alloc) ----
__device__ float g_q   [NN*NH*NN*DHD];   // [n][h][c][d]
__device__ float g_k   [NN*NH*NN*DHD];
__device__ float g_v   [NN*NH*NN*DHD];
__device__ float g_gate[NN*NN*NINNER];   // [n][i][e], post-sigmoid
__device__ float g_bias[NH*NN*NN];       // [h][i][j]
__device__ float g_ao  [NN*NN*NINNER];   // attn-out * gate
__device__ int   g_flags[2];             // [0]=swap ln pair, [1]=mask mode (0=f32,1=i32,2=u8)

// ---------------- packed f32x2 helpers (FFMA2: 2 MACs per issue) ------------
typedef unsigned long long ull;

__device__ __forceinline__ void ffma2(ull& d, ull a, ull b) {
    asm volatile("fma.rn.f32x2 %0, %1, %2, %0;" : "+l"(d) : "l"(a), "l"(b));
}
__device__ __forceinline__ ull pack2(float lo, float hi) {
    ull r; asm("mov.b64 %0, {%1, %2};" : "=l"(r) : "f"(lo), "f"(hi)); return r;
}
__device__ __forceinline__ float2 unpack2(ull v) {
    float2 r; asm("mov.b64 {%0, %1}, %2;" : "=f"(r.x), "=f"(r.y) : "l"(v)); return r;
}
__device__ __forceinline__ float hsum2(ull a) { float2 f = unpack2(a); return f.x + f.y; }

// ---------------- kernel 0: resolve input ambiguities on-device -------------
// lnA/lnB: the two 64-float buffers (presumed ln_w first). ln_w is all-ones in
// this problem; if lnA isn't all-ones but lnB is, flag a swap.
// mask dtype: scan first 4096 32-bit words (16 KB, valid for every candidate
// dtype since the mask has 65536 elements >= 1 byte each).
//   float32 0/1 -> words in {0, 0x3F800000}
//   int32   0/1 -> words in {0, 1}
//   bool bytes  -> words are packed 0x00/0x01 bytes (fails both tests w.h.p.)
__global__ void detect_kernel(const float* __restrict__ lnA,
                              const float* __restrict__ lnB,
                              const unsigned int* __restrict__ mask_w)
{
    __shared__ int sA, sB, sFloat, sInt;
    if (threadIdx.x == 0) { sA = 1; sB = 1; sFloat = 1; sInt = 1; }
    __syncthreads();
    if (threadIdx.x < 64) {
        if (lnA[threadIdx.x] != 1.0f) atomicAnd(&sA, 0);
        if (lnB[threadIdx.x] != 1.0f) atomicAnd(&sB, 0);
    }
    for (int i = threadIdx.x; i < 4096; i += 256) {
        unsigned int w = mask_w[i];
        if (w != 0u && w != 0x3F800000u) atomicAnd(&sFloat, 0);
        if (w > 1u)                       atomicAnd(&sInt, 0);
    }
    __syncthreads();
    if (threadIdx.x == 0) {
        g_flags[0] = (!sA && sB) ? 1 : 0;
        g_flags[1] = sFloat ? 0 : (sInt ? 1 : 2);
    }
}

// ---------------- kernel 1: LN + QKV/gate/bias projection -------------------
// grid 128 blocks (2 grid-rows each), 256 threads (one per column position).
// All 516x64 weights live in smem; h lives in registers (32 f32x2).
__global__ void __launch_bounds__(256, 1) prep_kernel(
    const float* __restrict__ z,
    const float* __restrict__ lnA, const float* __restrict__ lnB,
    const float* __restrict__ w_qkv, const float* __restrict__ w_bias,
    const float* __restrict__ w_gate)
{
    extern __shared__ float sm[];
    float* ws    = sm;                  // [NOUT][64]
    float* s_lnw = ws + NOUT * DD;
    float* s_lnb = s_lnw + DD;
    const int tid = threadIdx.x;

    const int swap = g_flags[0];
    const float* lnw = swap ? lnB : lnA;
    const float* lnb = swap ? lnA : lnB;

    for (int idx = tid; idx < 384 * DD; idx += 256) ws[idx]            = w_qkv[idx];
    for (int idx = tid; idx < 128 * DD; idx += 256) ws[384 * DD + idx] = w_gate[idx];
    for (int idx = tid; idx <   4 * DD; idx += 256) ws[512 * DD + idx] = w_bias[idx];
    if (tid < DD) { s_lnw[tid] = lnw[tid]; s_lnb[tid] = lnb[tid]; }
    __syncthreads();

    const int r0 = blockIdx.x * 2;
    const int c  = tid;

    ull h2[2][32];
    #pragma unroll
    for (int p = 0; p < 2; p++) {
        const float4* zp = (const float4*)(z + ((size_t)(r0 + p) * NN + c) * DD);
        float s = 0.f, sq = 0.f;
        #pragma unroll
        for (int k = 0; k < 16; k++) {
            float4 t = zp[k];
            s  += (t.x + t.y) + (t.z + t.w);
            sq += (t.x * t.x + t.y * t.y) + (t.z * t.z + t.w * t.w);
        }
        float mu  = s * (1.f / 64.f);
        float var = sq * (1.f / 64.f) - mu * mu;
        float rs  = rsqrtf(fmaxf(var, 0.f) + 1e-5f);
        #pragma unroll
        for (int k = 0; k < 16; k++) {             // second pass: L1 hits
            float4 t = zp[k];
            float a0 = (t.x - mu) * rs * s_lnw[4*k  ] + s_lnb[4*k  ];
            float a1 = (t.y - mu) * rs * s_lnw[4*k+1] + s_lnb[4*k+1];
            float a2 = (t.z - mu) * rs * s_lnw[4*k+2] + s_lnb[4*k+2];
            float a3 = (t.w - mu) * rs * s_lnw[4*k+3] + s_lnb[4*k+3];
            h2[p][2*k]   = pack2(a0, a1);
            h2[p][2*k+1] = pack2(a2, a3);
        }
    }

    for (int o = 0; o < NOUT; o++) {
        const ull* wr = (const ull*)(ws + o * DD);
        ull a0=0,a1=0,a2=0,a3=0, b0=0,b1=0,b2=0,b3=0;
        #pragma unroll
        for (int k = 0; k < 32; k += 4) {
            ull w0 = wr[k], w1 = wr[k+1], w2 = wr[k+2], w3 = wr[k+3];
            ffma2(a0, h2[0][k],   w0);  ffma2(b0, h2[1][k],   w0);
            ffma2(a1, h2[0][k+1], w1);  ffma2(b1, h2[1][k+1], w1);
            ffma2(a2, h2[0][k+2], w2);  ffma2(b2, h2[1][k+2], w2);
            ffma2(a3, h2[0][k+3], w3);  ffma2(b3, h2[1][k+3], w3);
        }
        float ra = (hsum2(a0) + hsum2(a1)) + (hsum2(a2) + hsum2(a3));
        float rb = (hsum2(b0) + hsum2(b1)) + (hsum2(b2) + hsum2(b3));

        if (o < 384) {
            int s   = o >> 7;          // 0=q 1=k 2=v
            int rem = o & 127;         // h*32 + d
            float* base = (s == 0) ? g_q : (s == 1) ? g_k : g_v;
            int hh = rem >> 5, d = rem & 31;
            base[(((r0    ) * NH + hh) * NN + c) * DHD + d] = ra;
            base[(((r0 + 1) * NH + hh) * NN + c) * DHD + d] = rb;
        } else if (o < 512) {
            int e = o - 384;
            g_gate[((size_t)(r0    ) * NN + c) * NINNER + e] = 1.f / (1.f + __expf(-ra));
            g_gate[((size_t)(r0 + 1) * NN + c) * NINNER + e] = 1.f / (1.f + __expf(-rb));
        } else {
            int hh = o - 512;
            g_bias[((size_t)hh * NN + r0    ) * NN + c] = ra;
            g_bias[((size_t)hh * NN + r0 + 1) * NN + c] = rb;
        }
    }
}

// ---------------- kernel 2: masked softmax attention + gate -----------------
// block = (n, head), 256 threads, thread i owns query row i.
// Fixed-max softmax: logits are O(1); masked -> -1e30 -> exp -> 0.
__global__ void __launch_bounds__(256, 2) attn_kernel(const void* __restrict__ maskp)
{
    extern __shared__ float sm[];
    float* ks   = sm;                  // [256][32]
    float* vs   = ks + NN * DHD;       // [256][32]
    float* madd = vs + NN * DHD;       // [256]
    const int n  = blockIdx.x, hh = blockIdx.y;
    const int tid = threadIdx.x;

    {
        const float4* kg = (const float4*)(g_k + (size_t)((n * NH + hh) * NN) * DHD);
        const float4* vg = (const float4*)(g_v + (size_t)((n * NH + hh) * NN) * DHD);
        float4* ks4 = (float4*)ks; float4* vs4 = (float4*)vs;
        #pragma unroll
        for (int t = 0; t < 8; t++) {
            ks4[tid + 256 * t] = kg[tid + 256 * t];
            vs4[tid + 256 * t] = vg[tid + 256 * t];
        }
        const int mode = g_flags[1];
        bool on;
        if (mode == 2)      on = ((const unsigned char*)maskp)[n * NN + tid] != 0;
        else if (mode == 1) on = ((const int*)maskp)[n * NN + tid] != 0;
        else                on = ((const float*)maskp)[n * NN + tid] != 0.f;
        madd[tid] = on ? 0.f : -1e30f;
    }
    __syncthreads();

    const int i = tid;
    ull q2[16];
    {
        const float4* qg = (const float4*)(g_q + (size_t)((n * NH + hh) * NN + i) * DHD);
        #pragma unroll
        for (int k = 0; k < 8; k++) {
            float4 t = qg[k];
            q2[2*k]   = pack2(t.x, t.y);
            q2[2*k+1] = pack2(t.z, t.w);
        }
    }
    const float* brow = g_bias + (size_t)(hh * NN + i) * NN;

    ull acc[16];
    #pragma unroll
    for (int k = 0; k < 16; k++) acc[k] = 0ull;
    float ssum = 0.f;

    for (int j0 = 0; j0 < NN; j0 += 4) {
        float4 b4 = *(const float4*)(brow + j0);
        float bb[4] = {b4.x, b4.y, b4.z, b4.w};
        #pragma unroll
        for (int jj = 0; jj < 4; jj++) {
            int j = j0 + jj;
            const ull* krow = (const ull*)(ks + j * DHD);   // broadcast LDS
            ull d0=0, d1=0, d2=0, d3=0;
            #pragma unroll
            for (int k = 0; k < 16; k += 4) {
                ffma2(d0, q2[k],   krow[k]);
                ffma2(d1, q2[k+1], krow[k+1]);
                ffma2(d2, q2[k+2], krow[k+2]);
                ffma2(d3, q2[k+3], krow[k+3]);
            }
            float dot = (hsum2(d0) + hsum2(d1)) + (hsum2(d2) + hsum2(d3));
            float s = dot * ATT_SCALE + bb[jj] + madd[j];
            float p = __expf(s);
            ssum += p;
            ull p2 = pack2(p, p);
            const ull* vrow = (const ull*)(vs + j * DHD);   // broadcast LDS
            #pragma unroll
            for (int k = 0; k < 16; k++) ffma2(acc[k], p2, vrow[k]);
        }
    }

    float inv = 1.f / ssum;
    const float2* grow = (const float2*)(g_gate + (size_t)(n * NN + i) * NINNER + hh * DHD);
    float2*       aop  = (float2*)      (g_ao   + (size_t)(n * NN + i) * NINNER + hh * DHD);
    #pragma unroll
    for (int k = 0; k < 16; k++) {
        float2 a = unpack2(acc[k]);
        float2 g = grow[k];
        float2 o; o.x = a.x * inv * g.x; o.y = a.y * inv * g.y;
        aop[k] = o;
    }
}

// ---------------- kernel 3: (attn_out * gate) @ w_out^T ---------------------
// block = 32 positions; warp w computes outputs [8w, 8w+8) for 32 positions.
// u smem stride 129 -> conflict-free per-lane reads; w_out reads broadcast.
__global__ void __launch_bounds__(256, 4) out_kernel(
    const float* __restrict__ w_out, float* __restrict__ out)
{
    extern __shared__ float sm[];
    float* ws = sm;                 // [64][128]
    float* us = ws + 64 * 128;      // [32][129]
    const int tid = threadIdx.x;

    for (int idx = tid; idx < 64 * 128; idx += 256) ws[idx] = w_out[idx];
    const int p0 = blockIdx.x * 32;
    for (int idx = tid; idx < 32 * 128; idx += 256) {
        int p = idx >> 7, e = idx & 127;
        us[p * 129 + e] = g_ao[(size_t)(p0 + p) * NINNER + e];
    }
    __syncthreads();

    const int warp = tid >> 5, lane = tid & 31;
    const int obase = warp * 8;
    float acc[8] = {0,0,0,0,0,0,0,0};
    const float* urow = us + lane * 129;
    #pragma unroll 4
    for (int e = 0; e < 128; e++) {
        float u = urow[e];
        #pragma unroll
        for (int o = 0; o < 8; o++) acc[o] += u * ws[(obase + o) * 128 + e];
    }
    float* op = out + (size_t)(p0 + lane) * DD + obase;
    #pragma unroll
    for (int o = 0; o < 8; o++) op[o] = acc[o];
}

// ---------------- launch -----------------------------------------------------
extern "C" void kernel_launch(void* const* d_in, const int* in_sizes, int n_in,
                              void* d_out, int out_size)
{
    // Resolve inputs by ELEMENT count (in_sizes is elements, not bytes):
    //   z      = 1*256*256*64 = 4194304   (unique; also accept 16777216 if a
    //                                      harness ever reports bytes)
    //   mask   = 65536
    //   w_qkv  = 3*128*64     = 24576
    //   w_bias = 4*64         = 256
    // Tie pairs: {ln_w, ln_b} both 64; {w_out, w_gate} both 8192.
    // Ordering scheme inferred from where z sits: index 0 -> dict/insertion
    // order (ln_w before ln_b, w_out before w_gate); otherwise assume
    // alphabetical metadata order (ln_b first, w_gate first). The ln pair is
    // additionally verified on-device by content (ln_w is all-ones).
    const float* z = 0; const void* maskp = 0;
    const float *w_qkv = 0, *w_bias = 0;
    int idx_z = -1, i64[2] = {-1, -1}, n64 = 0, i8k[2] = {-1, -1}, n8k = 0;
    for (int i = 0; i < n_in; i++) {
        int s = in_sizes[i];
        if      (s == 4194304 || s == 16777216) { z = (const float*)d_in[i]; idx_z = i; }
        else if (s == 65536)    { maskp = d_in[i]; }
        else if (s == 24576)    { w_qkv = (const float*)d_in[i]; }
        else if (s == 256)      { w_bias = (const float*)d_in[i]; }
        else if (s == 64   && n64 < 2) { i64[n64++] = i; }
        else if (s == 8192 && n8k < 2) { i8k[n8k++] = i; }
    }
    const bool alpha = (idx_z != 0);
    const float* lnA    = (const float*)d_in[alpha ? i64[1] : i64[0]];  // presumed ln_w
    const float* lnB    = (const float*)d_in[alpha ? i64[0] : i64[1]];  // presumed ln_b
    const float* w_out  = (const float*)d_in[alpha ? i8k[1] : i8k[0]];
    const float* w_gate = (const float*)d_in[alpha ? i8k[0] : i8k[1]];
    float* out = (float*)d_out;

    const int smem_prep = (NOUT * DD + 2 * DD) * 4;        // 132608 B
    const int smem_attn = (2 * NN * DHD + NN) * 4;         //  66560 B
    const int smem_out  = (64 * 128 + 32 * 129) * 4;       //  49280 B
    cudaFuncSetAttribute(prep_kernel, cudaFuncAttributeMaxDynamicSharedMemorySize, smem_prep);
    cudaFuncSetAttribute(attn_kernel, cudaFuncAttributeMaxDynamicSharedMemorySize, smem_attn);
    cudaFuncSetAttribute(out_kernel,  cudaFuncAttributeMaxDynamicSharedMemorySize, smem_out);

    detect_kernel<<<1, 256>>>(lnA, lnB, (const unsigned int*)maskp);
    prep_kernel<<<128, 256, smem_prep>>>(z, lnA, lnB, w_qkv, w_bias, w_gate);
    attn_kernel<<<dim3(NN, NH), 256, smem_attn>>>(maskp);
    out_kernel<<<NN * NN / 32, 256, smem_out>>>(w_out, out);
}